// round 11
// baseline (speedup 1.0000x reference)
#include <cuda_runtime.h>
#include <cuda_bf16.h>
#include <cstdint>

// PARAFAC / CP reconstruction: out[a,b,c] = sum_k f0[k,a]*f1[k,b]*f2[k,c]
// A=B=C=512, RANK=16, fp32 out (536 MB stores).
//
// Round-11: round-8 MMA mainloop (48 regs, occ 59%, fma-free; its only defect was
// 32B-scattered stores, L1 90%) + warp-private SMEM bounce epilogue:
//   - warp computes 4 n-blocks (16b x 32c), stages D-frags via STS.64 into
//     S[16][36] (pitch 36 floats: STS 2-phase, drain-LDS 4-phase, both conflict-free)
//   - drain: LDS.128 coalesced -> STG.128 (4 aligned 128B segments per warp instr)
//   - warp-private buffer -> __syncwarp only, no block barriers, no shuffles
//   - A-frags computed once per warp; B-quads from round-10-validated F2s layout
// L1 ~2.5 wf/128B (round 8: ~5), issue ~130 warp-instr/8KB (scalar: 656), fma ~0.

#define A_DIM 512
#define B_DIM 512
#define C_DIM 512
#define RANK  16
#define BTILE 64         // 4 warps x 16 b-rows
#define CTILE 128        // 16 n-blocks of 8 c
#define NTHREADS 128
#define SPITCH 36        // staging row pitch in floats (conflict-free)

__device__ __forceinline__ uint32_t bfpack(__nv_bfloat16 e0, __nv_bfloat16 e1) {
    __nv_bfloat162 p; p.x = e0; p.y = e1;
    return *reinterpret_cast<uint32_t*>(&p);
}
__device__ __forceinline__ void split_bf16(float v, __nv_bfloat16& hi, __nv_bfloat16& lo) {
    hi = __float2bfloat16(v);
    lo = __float2bfloat16(v - __bfloat162float(hi));
}
__device__ __forceinline__ void mma16816(float& d0, float& d1, float& d2, float& d3,
                                         uint32_t a0, uint32_t a1, uint32_t a2, uint32_t a3,
                                         uint32_t b0, uint32_t b1) {
    asm volatile(
        "mma.sync.aligned.m16n8k16.row.col.f32.bf16.bf16.f32 "
        "{%0,%1,%2,%3}, {%4,%5,%6,%7}, {%8,%9}, {%0,%1,%2,%3};"
        : "+f"(d0), "+f"(d1), "+f"(d2), "+f"(d3)
        : "r"(a0), "r"(a1), "r"(a2), "r"(a3), "r"(b0), "r"(b1));
}

__global__ __launch_bounds__(NTHREADS, 8)
void parafac_mma_kernel(const float* __restrict__ f0,
                        const float* __restrict__ f1,
                        const float* __restrict__ f2,
                        float* __restrict__ out)
{
    // F2 split tile (round-10 validated layout), per (c, qslot) 16B quad:
    //   {bh0, bh1, bl0, bl1}: bh0=hi(k=2q,2q+1), bh1=hi(k=2q+8,+9), bl*=lo(same)
    __shared__ __align__(16) unsigned char F2s[CTILE * 64];          // 8 KB
    // warp-private staging: 4 warps x 16 rows x 36 floats
    __shared__ __align__(16) float Sbuf[4][16][SPITCH];              // 9216 B

    const int a  = blockIdx.z;
    const int b0 = blockIdx.y * BTILE;
    const int c0 = blockIdx.x * CTILE;
    const int t  = threadIdx.x;
    const int w    = t >> 5;
    const int lane = t & 31;
    const int q    = lane & 3;
    const int r    = lane >> 2;

    // ---- stage F2 split tile (validated round 10) ----
    for (int i = t; i < CTILE * RANK; i += NTHREADS) {
        int k  = i >> 7;
        int cc = i & 127;            // contiguous over c -> coalesced LDG
        float v = f2[k * C_DIM + c0 + cc];
        __nv_bfloat16 hi, lo;
        split_bf16(v, hi, lo);
        int base = cc * 64 + ((k & 7) >> 1) * 16 + ((k >> 3) & 1) * 4 + (k & 1) * 2;
        *reinterpret_cast<__nv_bfloat16*>(F2s + base)     = hi;
        *reinterpret_cast<__nv_bfloat16*>(F2s + base + 8) = lo;
    }

    // ---- A fragments (g side), once per warp (coords validated round 8) ----
    const int br0 = b0 + w * 16 + r;
    const int br1 = br0 + 8;
    uint32_t ah[4], al[4];
    {
        const int ks[2] = { 2 * q, 2 * q + 8 };
#pragma unroll
        for (int h = 0; h < 2; h++) {
            int k0 = ks[h], k1 = ks[h] + 1;
            float ga0 = f0[k0 * A_DIM + a] * f1[k0 * B_DIM + br0];
            float ga1 = f0[k1 * A_DIM + a] * f1[k1 * B_DIM + br0];
            float gb0 = f0[k0 * A_DIM + a] * f1[k0 * B_DIM + br1];
            float gb1 = f0[k1 * A_DIM + a] * f1[k1 * B_DIM + br1];
            __nv_bfloat16 h0, l0, h1, l1;
            split_bf16(ga0, h0, l0); split_bf16(ga1, h1, l1);
            ah[2 * h + 0] = bfpack(h0, h1);
            al[2 * h + 0] = bfpack(l0, l1);
            split_bf16(gb0, h0, l0); split_bf16(gb1, h1, l1);
            ah[2 * h + 1] = bfpack(h0, h1);
            al[2 * h + 1] = bfpack(l0, l1);
        }
    }
    __syncthreads();   // F2s visible to all warps

    float (*S)[SPITCH] = Sbuf[w];
    float* oblk = out + (size_t)a * (B_DIM * C_DIM);
    const int rr = lane >> 3;      // drain: row-in-group 0..3
    const int cs = lane & 7;       // drain: 16B column slot 0..7

    // ---- 4 chunks of 4 n-blocks (32 c each) ----
#pragma unroll 1
    for (int chunk = 0; chunk < 4; chunk++) {
#pragma unroll
        for (int i = 0; i < 4; i++) {
            const int m = 4 * chunk + i;
            const uint4 bm = *reinterpret_cast<const uint4*>(F2s + (8 * m + r) * 64 + q * 16);

            float d0 = 0.f, d1 = 0.f, d2 = 0.f, d3 = 0.f;
            mma16816(d0, d1, d2, d3, ah[0], ah[1], ah[2], ah[3], bm.x, bm.y); // Ah*Bh
            mma16816(d0, d1, d2, d3, al[0], al[1], al[2], al[3], bm.x, bm.y); // Al*Bh
            mma16816(d0, d1, d2, d3, ah[0], ah[1], ah[2], ah[3], bm.z, bm.w); // Ah*Bl

            // stage: D[r][8i+2q..+1], D[r+8][same] (chunk-local c)
            *reinterpret_cast<float2*>(&S[r][8 * i + 2 * q])     = make_float2(d0, d1);
            *reinterpret_cast<float2*>(&S[r + 8][8 * i + 2 * q]) = make_float2(d2, d3);
        }
        __syncwarp();

        // ---- drain: 16 rows x 32 floats; 4 rows per pass, 8 lanes per row ----
        const int cbase = c0 + 32 * chunk;
#pragma unroll
        for (int g = 0; g < 4; g++) {
            const int row = 4 * g + rr;
            float4 v = *reinterpret_cast<const float4*>(&S[row][4 * cs]);
            const int b = b0 + 16 * w + row;
            *reinterpret_cast<float4*>(oblk + (size_t)b * C_DIM + cbase + 4 * cs) = v;
        }
        __syncwarp();   // before next chunk overwrites S
    }
}

extern "C" void kernel_launch(void* const* d_in, const int* in_sizes, int n_in,
                              void* d_out, int out_size)
{
    const float* f0 = (const float*)d_in[0];
    const float* f1 = (const float*)d_in[1];
    const float* f2 = (const float*)d_in[2];
    float* out = (float*)d_out;

    dim3 grid(C_DIM / CTILE, B_DIM / BTILE, A_DIM);   // (4, 8, 512) = 16384 blocks
    dim3 block(NTHREADS);
    parafac_mma_kernel<<<grid, block>>>(f0, f1, f2, out);
}

// round 12
// speedup vs baseline: 1.1461x; 1.1461x over previous
#include <cuda_runtime.h>
#include <cstdint>

// PARAFAC / CP reconstruction: out[a,b,c] = sum_k f0[k,a] * f1[k,b] * f2[k,c]
// A = B = C = 512, RANK = 16, fp32. 536 MB output.
//
// Round-12: scalar FFMA2 kernel with TWO c-quads per thread.
// Calibrated model: at 96us the kernel is two ~113K-cyc pipe workloads (fma rt2,
// L1 return-bound) interleaving at 66%. g-broadcast LDS is 2/3 of L1 work; feeding
// 1KB (not 512B) of output per g-reload cuts L1 work to 0.6x -> fma sole binder.
//   - thread owns quads at c=4s and c=256+4s: both warp-contiguous -> all STG.128
//     fully coalesced (4 sectors/instr)
//   - R2-style c-pair packing (f2r 32 regs/quad; k-pair packing would spill)
//   - per j per thread: 4 bcast LDS.128 + 16 splat movs + 64 FFMA2 + 6 ADD2 + 2 STG.128

#define A_DIM 512
#define B_DIM 512
#define C_DIM 512
#define RANK  16
#define BCHUNK 64
#define NTHREADS 64    // 64 threads x 2 quads x 4c = 512 c

typedef unsigned long long ull;

__global__ __launch_bounds__(NTHREADS, 8)
void parafac_kernel(const float* __restrict__ f0,
                    const float* __restrict__ f1,
                    const float* __restrict__ f2,
                    float* __restrict__ out)
{
    // g splat-free storage: gsh[j][k] = f0[k][a]*f1[k][b0+j]
    __shared__ __align__(16) float gsh[BCHUNK][RANK];

    const int a  = blockIdx.y;
    const int b0 = blockIdx.x * BCHUNK;
    const int s  = threadIdx.x;
    const int cA = 4 * s;          // quad A: c in [0,256)
    const int cB = 256 + 4 * s;    // quad B: c in [256,512)

    // ---- f2 packed per k as c-pairs (R2 layout), for both quads ----
    // f2rX[2k]   = (f2[k][c+0], f2[k][c+1]),  f2rX[2k+1] = (f2[k][c+2], f2[k][c+3])
    ull f2rA[2 * RANK], f2rB[2 * RANK];
#pragma unroll
    for (int k = 0; k < RANK; k++) {
        ulonglong2 va = *reinterpret_cast<const ulonglong2*>(f2 + k * C_DIM + cA);
        ulonglong2 vb = *reinterpret_cast<const ulonglong2*>(f2 + k * C_DIM + cB);
        f2rA[2 * k + 0] = va.x;  f2rA[2 * k + 1] = va.y;
        f2rB[2 * k + 0] = vb.x;  f2rB[2 * k + 1] = vb.y;
    }

    // ---- precompute g: 64*16 = 1024 entries, 64 threads -> 16 each ----
#pragma unroll
    for (int i = 0; i < (BCHUNK * RANK) / NTHREADS; i++) {
        int idx = s + i * NTHREADS;
        int j = idx >> 4;     // b offset within chunk
        int k = idx & 15;     // rank index
        gsh[j][k] = f0[k * A_DIM + a] * f1[k * B_DIM + b0 + j];
    }
    __syncthreads();

    float* orow = out + (size_t)a * (B_DIM * C_DIM) + (size_t)b0 * C_DIM;

#pragma unroll 1
    for (int j = 0; j < BCHUNK; j++) {
        // 4x LDS.128: 16 g floats (one reload feeds 1KB of output)
        const float4* gj4 = reinterpret_cast<const float4*>(gsh[j]);
        float4 q0 = gj4[0], q1 = gj4[1], q2 = gj4[2], q3 = gj4[3];
        float gf[RANK] = { q0.x, q0.y, q0.z, q0.w,
                           q1.x, q1.y, q1.z, q1.w,
                           q2.x, q2.y, q2.z, q2.w,
                           q3.x, q3.y, q3.z, q3.w };

        // quad A chains: aA0/aA1 = c-pair0 (k even/odd), bA0/bA1 = c-pair1
        ull aA0 = 0ull, aA1 = 0ull, bA0 = 0ull, bA1 = 0ull;
        ull aB0 = 0ull, aB1 = 0ull, bB0 = 0ull, bB1 = 0ull;

#pragma unroll
        for (int k = 0; k < RANK; k += 2) {
            ull gp0, gp1;
            asm("mov.b64 %0, {%1,%1};" : "=l"(gp0) : "r"(__float_as_uint(gf[k])));
            asm("mov.b64 %0, {%1,%1};" : "=l"(gp1) : "r"(__float_as_uint(gf[k + 1])));
            asm("fma.rn.f32x2 %0, %1, %2, %0;" : "+l"(aA0) : "l"(f2rA[2 * k + 0]), "l"(gp0));
            asm("fma.rn.f32x2 %0, %1, %2, %0;" : "+l"(bA0) : "l"(f2rA[2 * k + 1]), "l"(gp0));
            asm("fma.rn.f32x2 %0, %1, %2, %0;" : "+l"(aB0) : "l"(f2rB[2 * k + 0]), "l"(gp0));
            asm("fma.rn.f32x2 %0, %1, %2, %0;" : "+l"(bB0) : "l"(f2rB[2 * k + 1]), "l"(gp0));
            asm("fma.rn.f32x2 %0, %1, %2, %0;" : "+l"(aA1) : "l"(f2rA[2 * k + 2]), "l"(gp1));
            asm("fma.rn.f32x2 %0, %1, %2, %0;" : "+l"(bA1) : "l"(f2rA[2 * k + 3]), "l"(gp1));
            asm("fma.rn.f32x2 %0, %1, %2, %0;" : "+l"(aB1) : "l"(f2rB[2 * k + 2]), "l"(gp1));
            asm("fma.rn.f32x2 %0, %1, %2, %0;" : "+l"(bB1) : "l"(f2rB[2 * k + 3]), "l"(gp1));
        }

        ulonglong2 rA, rB;
        asm("add.rn.f32x2 %0, %1, %2;" : "=l"(rA.x) : "l"(aA0), "l"(aA1));
        asm("add.rn.f32x2 %0, %1, %2;" : "=l"(rA.y) : "l"(bA0), "l"(bA1));
        asm("add.rn.f32x2 %0, %1, %2;" : "=l"(rB.x) : "l"(aB0), "l"(aB1));
        asm("add.rn.f32x2 %0, %1, %2;" : "=l"(rB.y) : "l"(bB0), "l"(bB1));

        float* rp = orow + (size_t)j * C_DIM;
        *reinterpret_cast<ulonglong2*>(rp + cA) = rA;   // STG.128, coalesced
        *reinterpret_cast<ulonglong2*>(rp + cB) = rB;   // STG.128, coalesced
    }
}

extern "C" void kernel_launch(void* const* d_in, const int* in_sizes, int n_in,
                              void* d_out, int out_size)
{
    const float* f0 = (const float*)d_in[0];
    const float* f1 = (const float*)d_in[1];
    const float* f2 = (const float*)d_in[2];
    float* out = (float*)d_out;

    dim3 grid(B_DIM / BCHUNK, A_DIM);   // (8, 512) = 4096 blocks
    dim3 block(NTHREADS);
    parafac_kernel<<<grid, block>>>(f0, f1, f2, out);
}